// round 4
// baseline (speedup 1.0000x reference)
#include <cuda_runtime.h>
#include <cstdint>

#define Bv 256
#define Sv 2048
#define Tv 48

// -------- runtime format flags --------
__device__ int g_tags64;   // tags stored as int64 (JAX x64) vs int32
__device__ int g_mask32;   // mask stored as int32 (0/1 words) vs 1-byte bool

// -------- packed f32x2 helpers (sm_103a) --------
#define FMA2(d,a,b,c) asm("fma.rn.f32x2 %0, %1, %2, %3;" : "=l"(d) : "l"(a), "l"(b), "l"(c))
#define ADD2(d,a,b)   asm("add.rn.f32x2 %0, %1, %2;"     : "=l"(d) : "l"(a), "l"(b))
#define MUL2(d,a,b)   asm("mul.rn.f32x2 %0, %1, %2;"     : "=l"(d) : "l"(a), "l"(b))

static __device__ __forceinline__ unsigned long long pack2(float x, float y){
  unsigned long long r; asm("mov.b64 %0, {%1, %2};" : "=l"(r) : "f"(x), "f"(y)); return r;
}
static __device__ __forceinline__ void unpack2(float& x, float& y, unsigned long long v){
  asm("mov.b64 {%0, %1}, %2;" : "=f"(x), "=f"(y) : "l"(v));
}
static __device__ __forceinline__ float rcp_fast(float x){
  float r; asm("rcp.approx.f32 %0, %1;" : "=f"(r) : "f"(x)); return r;
}
static __device__ __forceinline__ int ld_mask(const void* mp, size_t idx, int m32){
  return m32 ? ((const int*)mp)[idx] : (int)((const unsigned char*)mp)[idx];
}

// Detect input formats.
// tags: values in [0,48); if int64, every odd 32-bit word of the first 256 is 0.
// mask: values 0/1; if int32, every 32-bit word is 0 or 1; a byte mask of ones
//       gives words 0x01010101 (>1). Any word >1 => byte mask.
__global__ void detect_fmt_kernel(const unsigned int* __restrict__ tw,
                                  const unsigned int* __restrict__ mw){
  if (threadIdx.x == 0){
    int is64 = 1;
    #pragma unroll 1
    for (int i = 1; i < 256; i += 2) if (tw[i] != 0u) { is64 = 0; break; }
    g_tags64 = is64;
    int m32 = 1;
    #pragma unroll 1
    for (int i = 0; i < 512; ++i) if (mw[i] > 1u) { m32 = 0; break; }
    g_mask32 = m32;
  }
}

// -------- gold-path score: one warp per batch element --------
__global__ void __launch_bounds__(32) crf_score_kernel(
    const float* __restrict__ em_all, const void* __restrict__ tagsv,
    const void* __restrict__ maskp, const float* __restrict__ trans,
    const float* __restrict__ startv, const float* __restrict__ endv,
    float* __restrict__ out)
{
  const int b = blockIdx.x;
  const int L = threadIdx.x;
  const float* em = em_all + (size_t)b * (Sv * Tv);
  const long long* t64 = (const long long*)tagsv;
  const int*       t32 = (const int*)tagsv;
  const int is64 = g_tags64;
  const int m32  = g_mask32;
  const size_t base = (size_t)b * Sv;

  float acc = 0.f;
  int cnt = 0;
  for (int s = L; s < Sv; s += 32){
    int ts = is64 ? (int)t64[base + s] : t32[base + s];
    int m  = ld_mask(maskp, base + s, m32);
    cnt += m;
    if (s > 0 && m){
      int tp = is64 ? (int)t64[base + s - 1] : t32[base + s - 1];
      acc += trans[tp * Tv + ts] + em[s * Tv + ts];
    }
  }
  #pragma unroll
  for (int o = 16; o; o >>= 1){
    acc += __shfl_xor_sync(0xffffffffu, acc, o);
    cnt += __shfl_xor_sync(0xffffffffu, cnt, o);
  }
  if (L == 0){
    int tg0 = is64 ? (int)t64[base] : t32[base];
    float sc = startv[tg0] + em[tg0] + acc;
    int last = cnt - 1;
    int tl = is64 ? (int)t64[base + last] : t32[base + last];
    sc += endv[tl];
    out[b] = -sc;                 // forward kernel adds the log-partition
  }
}

// -------- forward (log-partition): one warp per batch element --------
// Lanes 0..23 own tag pairs (t0=2L, t0+1). Linear-space matvec with packed
// f32x2 FMAs. STABLE normalization:
//   p'_t = (d_t * rcp(d_0)) * exp(em_t - em_0)    (current-step d_0 -> p_0 == 1,
//                                                  zero drift, no feedback)
//   M   += em_0 + log(d_0)                         (pure accumulator, off-path)
// The exp(em_t - em_0) factors depend ONLY on emissions, so they are
// precomputed one step ahead (off the serial critical path).
__global__ void __launch_bounds__(32) crf_forward_kernel(
    const float* __restrict__ em_all,
    const void* __restrict__ maskp,
    const float* __restrict__ trans,
    const float* __restrict__ startv,
    const float* __restrict__ endv,
    float* __restrict__ out)
{
  const int b = blockIdx.x;
  const int L = threadIdx.x;
  const bool act = (L < 24);
  const int t0 = act ? 2 * L : 0;
  const int t1 = t0 + 1;
  const float* em = em_all + (size_t)b * (Sv * Tv);
  const size_t mbase = (size_t)b * Sv;
  const int m32 = g_mask32;

  __shared__ float4 pdup[2][24];   // pdup[buf][L] = {p_{2L}, p_{2L}, p_{2L+1}, p_{2L+1}}

  // E columns for this lane's two tags: E[j][t] = exp(transitions[j][t])
  unsigned long long ecol[Tv];
  #pragma unroll
  for (int j = 0; j < Tv; ++j){
    float ex = __expf(trans[j * Tv + t0]);
    float ey = __expf(trans[j * Tv + t1]);
    ecol[j] = pack2(ex, ey);
  }

  // init: alpha0 = start + em[0,:]; normalize by alpha0[tag 0]
  float a0 = startv[t0] + em[t0];
  float a1 = startv[t1] + em[t1];
  float aref = __shfl_sync(0xffffffffu, a0, 0);
  float p0 = __expf(a0 - aref);
  float p1 = __expf(a1 - aref);
  double Macc = (double)aref;
  if (act) pdup[0][L] = make_float4(p0, p0, p1, p1);
  __syncwarp();

  // emissions prefetch pipeline, depth 4 (covers ~577cyc DRAM latency)
  float2 e2buf[4];
  int mbuf[4];
  #pragma unroll
  for (int k = 0; k < 4; ++k){
    int s = 1 + k;
    e2buf[k] = *(const float2*)(em + s * Tv + t0);
    mbuf[k] = ld_mask(maskp, mbase + s, m32);
  }

  // bootstrap step-1 emission factors: eoff_t = exp(em[1,t] - em[1,0])
  float erefCur = __shfl_sync(0xffffffffu, e2buf[0].x, 0);
  unsigned long long eoffP = pack2(__expf(e2buf[0].x - erefCur),
                                   __expf(e2buf[0].y - erefCur));

  int buf = 0;
  #pragma unroll 4
  for (int s = 1; s < Sv; ++s){
    const int k = (s - 1) & 3;               // slot holding step s (mask) — consumed now
    const float2 e2n = e2buf[s & 3];         // slot holding step s+1 emissions
    const int m = mbuf[k];
    // refill slot k with step s+4 (clamped; harmless redundant loads at the tail)
    int sn = s + 4; if (sn > Sv - 1) sn = Sv - 1;
    e2buf[k] = *(const float2*)(em + sn * Tv + t0);
    mbuf[k] = ld_mask(maskp, mbase + sn, m32);

    // matvec: d_t = sum_j p_j * E[j][t]  (p broadcast from shared, duplicated pairs)
    unsigned long long acc0 = 0ull, acc1 = 0ull, acc2 = 0ull, acc3 = 0ull;
    const ulonglong2* pp = (const ulonglong2*)&pdup[buf][0];
    #pragma unroll
    for (int jj = 0; jj < 24; jj += 2){
      ulonglong2 va = pp[jj];
      ulonglong2 vb = pp[jj + 1];
      FMA2(acc0, va.x, ecol[2 * jj + 0], acc0);
      FMA2(acc1, va.y, ecol[2 * jj + 1], acc1);
      FMA2(acc2, vb.x, ecol[2 * jj + 2], acc2);
      FMA2(acc3, vb.y, ecol[2 * jj + 3], acc3);
    }
    ADD2(acc0, acc0, acc1);
    ADD2(acc2, acc2, acc3);
    ADD2(acc0, acc0, acc2);

    // q = d * exp(em - em0)   (independent of rcp -> overlaps the shfl)
    unsigned long long q;
    MUL2(q, acc0, eoffP);

    // current-step normalizer: r = 1/d_0 (lane 0 low half); p = q * r
    float d0lo, d0hi; unpack2(d0lo, d0hi, acc0);
    float dref = __shfl_sync(0xffffffffu, d0lo, 0);
    float r = rcp_fast(dref);
    unsigned long long rdup = pack2(r, r);
    unsigned long long pnew;
    MUL2(pnew, q, rdup);
    float np0, np1; unpack2(np0, np1, pnew);

    if (m){ p0 = np0; p1 = np1; Macc += (double)(erefCur + __logf(dref)); }
    if (act) pdup[buf ^ 1][L] = make_float4(p0, p0, p1, p1);
    buf ^= 1;

    // prepare NEXT step's emission factors (emissions only — no feedback, stable)
    float erefN = __shfl_sync(0xffffffffu, e2n.x, 0);
    eoffP = pack2(__expf(e2n.x - erefN), __expf(e2n.y - erefN));
    erefCur = erefN;

    __syncwarp();
  }

  // norm = M + log( sum_t p_t * exp(end_t) )
  float w = 0.f;
  if (act) w = p0 * __expf(endv[t0]) + p1 * __expf(endv[t1]);
  #pragma unroll
  for (int o = 16; o; o >>= 1) w += __shfl_xor_sync(0xffffffffu, w, o);
  if (L == 0) out[b] += (float)(Macc + (double)__logf(w));
}

extern "C" void kernel_launch(void* const* d_in, const int* in_sizes, int n_in,
                              void* d_out, int out_size)
{
  const float* emissions       = (const float*)d_in[0];
  const void* tags             = d_in[1];
  const void* mask             = d_in[2];
  const float* trans           = (const float*)d_in[3];
  const float* startv          = (const float*)d_in[4];
  const float* endv            = (const float*)d_in[5];
  float* out                   = (float*)d_out;

  detect_fmt_kernel<<<1, 32>>>((const unsigned int*)tags, (const unsigned int*)mask);
  crf_score_kernel  <<<Bv, 32>>>(emissions, tags, mask, trans, startv, endv, out);
  crf_forward_kernel<<<Bv, 32>>>(emissions, mask, trans, startv, endv, out);
}

// round 5
// speedup vs baseline: 1.2246x; 1.2246x over previous
#include <cuda_runtime.h>
#include <cstdint>

#define Bv 256
#define Sv 2048
#define Tv 48

// -------- runtime format flags --------
__device__ int g_tags64;   // tags stored as int64 (JAX x64) vs int32
__device__ int g_mask32;   // mask stored as int32 (0/1 words) vs 1-byte bool

// -------- packed f32x2 helpers (sm_103a) --------
#define FMA2(d,a,b,c) asm("fma.rn.f32x2 %0, %1, %2, %3;" : "=l"(d) : "l"(a), "l"(b), "l"(c))
#define ADD2(d,a,b)   asm("add.rn.f32x2 %0, %1, %2;"     : "=l"(d) : "l"(a), "l"(b))
#define MUL2(d,a,b)   asm("mul.rn.f32x2 %0, %1, %2;"     : "=l"(d) : "l"(a), "l"(b))

static __device__ __forceinline__ unsigned long long pack2(float x, float y){
  unsigned long long r; asm("mov.b64 %0, {%1, %2};" : "=l"(r) : "f"(x), "f"(y)); return r;
}
static __device__ __forceinline__ void unpack2(float& x, float& y, unsigned long long v){
  asm("mov.b64 {%0, %1}, %2;" : "=f"(x), "=f"(y) : "l"(v));
}
static __device__ __forceinline__ float rcp_fast(float x){
  float r; asm("rcp.approx.f32 %0, %1;" : "=f"(r) : "f"(x)); return r;
}
static __device__ __forceinline__ int ld_mask(const void* mp, size_t idx, int m32){
  return m32 ? ((const int*)mp)[idx] : (int)((const unsigned char*)mp)[idx];
}

// Parallel format detection (one warp; ~2us instead of 36us single-thread).
// tags: values in [0,48); int64 <=> every odd 32-bit word of first 256 is 0.
// mask: 0/1 values; int32 <=> every 32-bit word of first 512 is <= 1.
__global__ void __launch_bounds__(32) detect_fmt_kernel(
    const unsigned int* __restrict__ tw, const unsigned int* __restrict__ mw){
  const int L = threadIdx.x;
  unsigned int bad64 = 0, badm = 0;
  #pragma unroll
  for (int i = 1 + 2 * L; i < 256; i += 64) bad64 |= (tw[i] != 0u);
  #pragma unroll
  for (int i = L; i < 512; i += 32)         badm  |= (mw[i] > 1u);
  bad64 = __any_sync(0xffffffffu, bad64);
  badm  = __any_sync(0xffffffffu, badm);
  if (L == 0){ g_tags64 = !bad64; g_mask32 = !badm; }
}

// -------- gold-path score: one warp per batch element --------
__global__ void __launch_bounds__(32) crf_score_kernel(
    const float* __restrict__ em_all, const void* __restrict__ tagsv,
    const void* __restrict__ maskp, const float* __restrict__ trans,
    const float* __restrict__ startv, const float* __restrict__ endv,
    float* __restrict__ out)
{
  const int b = blockIdx.x;
  const int L = threadIdx.x;
  const float* em = em_all + (size_t)b * (Sv * Tv);
  const long long* t64 = (const long long*)tagsv;
  const int*       t32 = (const int*)tagsv;
  const int is64 = g_tags64;
  const int m32  = g_mask32;
  const size_t base = (size_t)b * Sv;

  float acc = 0.f;
  int cnt = 0;
  #pragma unroll 4
  for (int s = L; s < Sv; s += 32){
    int ts = is64 ? (int)t64[base + s] : t32[base + s];
    int m  = ld_mask(maskp, base + s, m32);
    cnt += m;
    if (s > 0 && m){
      int tp = is64 ? (int)t64[base + s - 1] : t32[base + s - 1];
      acc += trans[tp * Tv + ts] + em[s * Tv + ts];
    }
  }
  #pragma unroll
  for (int o = 16; o; o >>= 1){
    acc += __shfl_xor_sync(0xffffffffu, acc, o);
    cnt += __shfl_xor_sync(0xffffffffu, cnt, o);
  }
  if (L == 0){
    int tg0 = is64 ? (int)t64[base] : t32[base];
    float sc = startv[tg0] + em[tg0] + acc;
    int last = cnt - 1;
    int tl = is64 ? (int)t64[base + last] : t32[base + last];
    sc += endv[tl];
    out[b] = -sc;                 // forward kernel adds the log-partition
  }
}

// -------- forward (log-partition): one warp per batch element --------
// Lanes 0..23 own tag pairs (t0=2L, t0+1). Linear-space matvec with packed
// f32x2 FMAs. Stable normalization, applied EVERY OTHER step:
//   norm step:  p'_t = (d_t * rcp(d_0)) * exp(em_t - em_0);  M += em_0 + log(d_0)
//   skip step:  p'_t =  d_t             * exp(em_t - em_0);  M += em_0
// p_0 resets to ~1 at each norm step -> zero drift; one skipped step keeps
// |log p| < ~30, far inside fp32 range. exp(em_t - em_0) uses emissions only
// and is precomputed one step ahead (off the serial critical path).
// Prefetch pipeline uses 4 NAMED register slots (hand-unrolled x4) so nothing
// can fall into local memory.
__global__ void __launch_bounds__(32, 1) crf_forward_kernel(
    const float* __restrict__ em_all,
    const void* __restrict__ maskp,
    const float* __restrict__ trans,
    const float* __restrict__ startv,
    const float* __restrict__ endv,
    float* __restrict__ out)
{
  const int b = blockIdx.x;
  const int L = threadIdx.x;
  const bool act = (L < 24);
  const int t0 = act ? 2 * L : 0;
  const int t1 = t0 + 1;
  const float* em = em_all + (size_t)b * (Sv * Tv);
  const size_t mbase = (size_t)b * Sv;
  const int m32 = g_mask32;

  __shared__ float4 pdup[2][24];   // pdup[buf][L] = {p_{2L}, p_{2L}, p_{2L+1}, p_{2L+1}}

  // E columns for this lane's two tags: E[j][t] = exp(transitions[j][t])
  unsigned long long ecol[Tv];
  #pragma unroll
  for (int j = 0; j < Tv; ++j){
    float ex = __expf(trans[j * Tv + t0]);
    float ey = __expf(trans[j * Tv + t1]);
    ecol[j] = pack2(ex, ey);
  }

  // init: alpha0 = start + em[0,:]; normalize by alpha0[tag 0]
  float a0 = startv[t0] + em[t0];
  float a1 = startv[t1] + em[t1];
  float aref = __shfl_sync(0xffffffffu, a0, 0);
  float p0 = __expf(a0 - aref);
  float p1 = __expf(a1 - aref);
  double Macc = (double)aref;
  if (act) pdup[0][L] = make_float4(p0, p0, p1, p1);
  __syncwarp();

  // prefetch slots (steps 1..4) — NAMED registers, never array-indexed
  float2 e0 = *(const float2*)(em + 1 * Tv + t0);
  float2 e1 = *(const float2*)(em + 2 * Tv + t0);
  float2 e2 = *(const float2*)(em + 3 * Tv + t0);
  float2 e3 = *(const float2*)(em + 4 * Tv + t0);
  int m0 = ld_mask(maskp, mbase + 1, m32);
  int m1 = ld_mask(maskp, mbase + 2, m32);
  int m2 = ld_mask(maskp, mbase + 3, m32);
  int m3 = ld_mask(maskp, mbase + 4, m32);

  // bootstrap step-1 emission factors: eoff_t = exp(em[1,t] - em[1,0])
  float erefCur = __shfl_sync(0xffffffffu, e0.x, 0);
  unsigned long long eoffP = pack2(__expf(e0.x - erefCur),
                                   __expf(e0.y - erefCur));
  int buf = 0;

  // One forward step. EK/MK: slot holding this step's (refilled) data.
  // EN: slot holding NEXT step's emissions. SCUR: this step's index.
  #define STEP(EK, MK, EN, SCUR, DO_NORM)                                   \
  {                                                                          \
    const int m_ = MK;                                                       \
    const float2 en_ = EN;                                                   \
    int sn_ = (SCUR) + 4; if (sn_ > Sv - 1) sn_ = Sv - 1;                    \
    EK = *(const float2*)(em + (size_t)sn_ * Tv + t0);                       \
    MK = ld_mask(maskp, mbase + sn_, m32);                                   \
    unsigned long long acc0 = 0ull, acc1 = 0ull, acc2 = 0ull, acc3 = 0ull;   \
    const ulonglong2* pp_ = (const ulonglong2*)&pdup[buf][0];                \
    _Pragma("unroll")                                                        \
    for (int jj = 0; jj < 24; jj += 2){                                      \
      ulonglong2 va = pp_[jj];                                               \
      ulonglong2 vb = pp_[jj + 1];                                           \
      FMA2(acc0, va.x, ecol[2 * jj + 0], acc0);                              \
      FMA2(acc1, va.y, ecol[2 * jj + 1], acc1);                              \
      FMA2(acc2, vb.x, ecol[2 * jj + 2], acc2);                              \
      FMA2(acc3, vb.y, ecol[2 * jj + 3], acc3);                              \
    }                                                                        \
    ADD2(acc0, acc0, acc1);                                                  \
    ADD2(acc2, acc2, acc3);                                                  \
    ADD2(acc0, acc0, acc2);                                                  \
    unsigned long long q_;                                                   \
    MUL2(q_, acc0, eoffP);                                                   \
    float mupd_ = erefCur;                                                   \
    if (DO_NORM){                                                            \
      float d0lo_, d0hi_; unpack2(d0lo_, d0hi_, acc0);                       \
      float dref_ = __shfl_sync(0xffffffffu, d0lo_, 0);                      \
      float r_ = rcp_fast(dref_);                                            \
      unsigned long long rd_ = pack2(r_, r_);                                \
      MUL2(q_, q_, rd_);                                                     \
      mupd_ += __logf(dref_);                                                \
    }                                                                        \
    float np0_, np1_; unpack2(np0_, np1_, q_);                               \
    if (m_){ p0 = np0_; p1 = np1_; Macc += (double)mupd_; }                  \
    if (act) pdup[buf ^ 1][L] = make_float4(p0, p0, p1, p1);                 \
    buf ^= 1;                                                                \
    float erefN_ = __shfl_sync(0xffffffffu, en_.x, 0);                       \
    eoffP = pack2(__expf(en_.x - erefN_), __expf(en_.y - erefN_));           \
    erefCur = erefN_;                                                        \
    __syncwarp();                                                            \
  }

  // 511 full groups of 4 steps (s = 1..2044), then 3-step tail (2045..2047).
  #pragma unroll 1
  for (int g = 0; g < 511; ++g){
    const int s = 1 + 4 * g;
    STEP(e0, m0, e1, s + 0, false)
    STEP(e1, m1, e2, s + 1, true)
    STEP(e2, m2, e3, s + 2, false)
    STEP(e3, m3, e0, s + 3, true)
  }
  STEP(e0, m0, e1, 2045, false)
  STEP(e1, m1, e2, 2046, true)
  STEP(e2, m2, e3, 2047, false)
  #undef STEP

  // norm = M + log( sum_t p_t * exp(end_t) )
  float w = 0.f;
  if (act) w = p0 * __expf(endv[t0]) + p1 * __expf(endv[t1]);
  #pragma unroll
  for (int o = 16; o; o >>= 1) w += __shfl_xor_sync(0xffffffffu, w, o);
  if (L == 0) out[b] += (float)(Macc + (double)__logf(w));
}

extern "C" void kernel_launch(void* const* d_in, const int* in_sizes, int n_in,
                              void* d_out, int out_size)
{
  const float* emissions       = (const float*)d_in[0];
  const void* tags             = d_in[1];
  const void* mask             = d_in[2];
  const float* trans           = (const float*)d_in[3];
  const float* startv          = (const float*)d_in[4];
  const float* endv            = (const float*)d_in[5];
  float* out                   = (float*)d_out;

  detect_fmt_kernel<<<1, 32>>>((const unsigned int*)tags, (const unsigned int*)mask);
  crf_score_kernel  <<<Bv, 32>>>(emissions, tags, mask, trans, startv, endv, out);
  crf_forward_kernel<<<Bv, 32>>>(emissions, mask, trans, startv, endv, out);
}

// round 6
// speedup vs baseline: 1.3055x; 1.0660x over previous
#include <cuda_runtime.h>
#include <cstdint>

#define Bv 256
#define Sv 2048
#define Tv 48

// -------- runtime format flags --------
__device__ int g_tags64;   // tags stored as int64 (JAX x64) vs int32
__device__ int g_mask32;   // mask stored as int32 (0/1 words) vs 1-byte bool

// -------- packed f32x2 helpers (sm_103a) --------
#define FMA2(d,a,b,c) asm("fma.rn.f32x2 %0, %1, %2, %3;" : "=l"(d) : "l"(a), "l"(b), "l"(c))
#define ADD2(d,a,b)   asm("add.rn.f32x2 %0, %1, %2;"     : "=l"(d) : "l"(a), "l"(b))
#define MUL2(d,a,b)   asm("mul.rn.f32x2 %0, %1, %2;"     : "=l"(d) : "l"(a), "l"(b))

static __device__ __forceinline__ unsigned long long pack2(float x, float y){
  unsigned long long r; asm("mov.b64 %0, {%1, %2};" : "=l"(r) : "f"(x), "f"(y)); return r;
}
static __device__ __forceinline__ void unpack2(float& x, float& y, unsigned long long v){
  asm("mov.b64 {%0, %1}, %2;" : "=f"(x), "=f"(y) : "l"(v));
}
static __device__ __forceinline__ float rcp_fast(float x){
  float r; asm("rcp.approx.f32 %0, %1;" : "=f"(r) : "f"(x)); return r;
}
static __device__ __forceinline__ int ld_mask(const void* mp, size_t idx, int m32){
  return m32 ? ((const int*)mp)[idx] : (int)((const unsigned char*)mp)[idx];
}

// Parallel format detection (one warp).
// tags: values in [0,48); int64 <=> every odd 32-bit word of first 256 is 0.
// mask: 0/1 values; int32 <=> every 32-bit word of first 512 is <= 1.
__global__ void __launch_bounds__(32) detect_fmt_kernel(
    const unsigned int* __restrict__ tw, const unsigned int* __restrict__ mw){
  const int L = threadIdx.x;
  unsigned int bad64 = 0, badm = 0;
  #pragma unroll
  for (int i = 1 + 2 * L; i < 256; i += 64) bad64 |= (tw[i] != 0u);
  #pragma unroll
  for (int i = L; i < 512; i += 32)         badm  |= (mw[i] > 1u);
  bad64 = __any_sync(0xffffffffu, bad64);
  badm  = __any_sync(0xffffffffu, badm);
  if (L == 0){ g_tags64 = !bad64; g_mask32 = !badm; }
}

// ==== combined kernel: warp 0 = forward recurrence, warp 1 = gold-path score ====
// Forward (warp 0): lanes 0..23 own tag pairs (t0=2L, t0+1). Linear-space
// matvec with packed f32x2 FMAs. Stable skip-and-reset normalization, cadence 4:
//   norm step (s%4==1):  p' = (d * rcp(d_0)) * exp(em - em_0);  M += em_0 + log(d_0)
//   other steps:         p' =  d             * exp(em - em_0);  M += em_0
// p_0 resets to ~1 at each norm step -> zero drift; <=3 growth steps keep
// |log p| < ~55, inside fp32 range. The exp(em - em_0) factors depend only on
// emissions and are computed ONE STEP AHEAD at the TOP of the step, so their
// shfl+MUFU latency hides under the matvec issue stream.
__global__ void __launch_bounds__(64, 1) crf_fused_kernel(
    const float* __restrict__ em_all,
    const void* __restrict__ tagsv,
    const void* __restrict__ maskp,
    const float* __restrict__ trans,
    const float* __restrict__ startv,
    const float* __restrict__ endv,
    float* __restrict__ out)
{
  const int b = blockIdx.x;
  const int tid = threadIdx.x;
  const int m32 = g_mask32;
  const float* em = em_all + (size_t)b * (Sv * Tv);
  const size_t mbase = (size_t)b * Sv;

  __shared__ float4 pdup[2][24];   // pdup[buf][L] = {p_{2L}, p_{2L}, p_{2L+1}, p_{2L+1}}
  __shared__ float s_score;
  __shared__ double s_norm;

  if (tid >= 32){
    // ---------------- warp 1: gold-path score ----------------
    const int L = tid - 32;
    const long long* t64 = (const long long*)tagsv;
    const int*       t32 = (const int*)tagsv;
    const int is64 = g_tags64;

    float acc = 0.f;
    int cnt = 0;
    #pragma unroll 4
    for (int s = L; s < Sv; s += 32){
      int ts = is64 ? (int)t64[mbase + s] : t32[mbase + s];
      int m  = ld_mask(maskp, mbase + s, m32);
      cnt += m;
      if (s > 0 && m){
        int tp = is64 ? (int)t64[mbase + s - 1] : t32[mbase + s - 1];
        acc += trans[tp * Tv + ts] + em[s * Tv + ts];
      }
    }
    #pragma unroll
    for (int o = 16; o; o >>= 1){
      acc += __shfl_xor_sync(0xffffffffu, acc, o);
      cnt += __shfl_xor_sync(0xffffffffu, cnt, o);
    }
    if (L == 0){
      int tg0 = is64 ? (int)t64[mbase] : t32[mbase];
      float sc = startv[tg0] + em[tg0] + acc;
      int last = cnt - 1;
      int tl = is64 ? (int)t64[mbase + last] : t32[mbase + last];
      sc += endv[tl];
      s_score = -sc;
    }
  } else {
    // ---------------- warp 0: forward log-partition ----------------
    const int L = tid;
    const bool act = (L < 24);
    const int t0 = act ? 2 * L : 0;
    const int t1 = t0 + 1;

    // E columns for this lane's two tags: E[j][t] = exp(transitions[j][t])
    unsigned long long ecol[Tv];
    #pragma unroll
    for (int j = 0; j < Tv; ++j){
      float ex = __expf(trans[j * Tv + t0]);
      float ey = __expf(trans[j * Tv + t1]);
      ecol[j] = pack2(ex, ey);
    }

    // init: alpha0 = start + em[0,:]; normalize by alpha0[tag 0]
    float a0 = startv[t0] + em[t0];
    float a1 = startv[t1] + em[t1];
    float aref = __shfl_sync(0xffffffffu, a0, 0);
    float p0 = __expf(a0 - aref);
    float p1 = __expf(a1 - aref);
    double Macc = (double)aref;
    if (act) pdup[0][L] = make_float4(p0, p0, p1, p1);
    __syncwarp();

    // prefetch slots (steps 1..4) — NAMED registers, never array-indexed
    float2 e0 = *(const float2*)(em + 1 * Tv + t0);
    float2 e1 = *(const float2*)(em + 2 * Tv + t0);
    float2 e2 = *(const float2*)(em + 3 * Tv + t0);
    float2 e3 = *(const float2*)(em + 4 * Tv + t0);
    int m0 = ld_mask(maskp, mbase + 1, m32);
    int m1 = ld_mask(maskp, mbase + 2, m32);
    int m2 = ld_mask(maskp, mbase + 3, m32);
    int m3 = ld_mask(maskp, mbase + 4, m32);

    // bootstrap step-1 emission factors: eoff_t = exp(em[1,t] - em[1,0])
    float erefCur = __shfl_sync(0xffffffffu, e0.x, 0);
    unsigned long long eoffCur = pack2(__expf(e0.x - erefCur),
                                       __expf(e0.y - erefCur));
    int buf = 0;

    // One forward step. EK/MK: slot holding this step's (refilled) data.
    // EN: slot holding NEXT step's emissions. SCUR: this step's index.
    // eoff for the NEXT step is computed FIRST so shfl+MUFU hide under matvec.
    #define STEP(EK, MK, EN, SCUR, DO_NORM)                                   \
    {                                                                          \
      const int m_ = MK;                                                       \
      int sn_ = (SCUR) + 4; if (sn_ > Sv - 1) sn_ = Sv - 1;                    \
      EK = *(const float2*)(em + (size_t)sn_ * Tv + t0);                       \
      MK = ld_mask(maskp, mbase + sn_, m32);                                   \
      const float2 en_ = EN;                                                   \
      float erefN_ = __shfl_sync(0xffffffffu, en_.x, 0);                       \
      unsigned long long eoffN_ = pack2(__expf(en_.x - erefN_),                \
                                        __expf(en_.y - erefN_));               \
      unsigned long long acc0 = 0ull, acc1 = 0ull, acc2 = 0ull, acc3 = 0ull;   \
      const ulonglong2* pp_ = (const ulonglong2*)&pdup[buf][0];                \
      _Pragma("unroll")                                                        \
      for (int jj = 0; jj < 24; jj += 2){                                      \
        ulonglong2 va = pp_[jj];                                               \
        ulonglong2 vb = pp_[jj + 1];                                           \
        FMA2(acc0, va.x, ecol[2 * jj + 0], acc0);                              \
        FMA2(acc1, va.y, ecol[2 * jj + 1], acc1);                              \
        FMA2(acc2, vb.x, ecol[2 * jj + 2], acc2);                              \
        FMA2(acc3, vb.y, ecol[2 * jj + 3], acc3);                              \
      }                                                                        \
      ADD2(acc0, acc0, acc1);                                                  \
      ADD2(acc2, acc2, acc3);                                                  \
      ADD2(acc0, acc0, acc2);                                                  \
      unsigned long long q_;                                                   \
      MUL2(q_, acc0, eoffCur);                                                 \
      float mupd_ = erefCur;                                                   \
      if (DO_NORM){                                                            \
        float d0lo_, d0hi_; unpack2(d0lo_, d0hi_, acc0);                       \
        float dref_ = __shfl_sync(0xffffffffu, d0lo_, 0);                      \
        float r_ = rcp_fast(dref_);                                            \
        unsigned long long rd_ = pack2(r_, r_);                                \
        MUL2(q_, q_, rd_);                                                     \
        mupd_ += __logf(dref_);                                                \
      }                                                                        \
      float np0_, np1_; unpack2(np0_, np1_, q_);                               \
      if (m_){ p0 = np0_; p1 = np1_; Macc += (double)mupd_; }                  \
      if (act) pdup[buf ^ 1][L] = make_float4(p0, p0, p1, p1);                 \
      buf ^= 1;                                                                \
      eoffCur = eoffN_; erefCur = erefN_;                                      \
      __syncwarp();                                                            \
    }

    // 511 full groups of 4 steps (s = 1..2044), then 3-step tail (2045..2047).
    // Norm on s % 4 == 1 (first step of each group and first tail step).
    #pragma unroll 1
    for (int g = 0; g < 511; ++g){
      const int s = 1 + 4 * g;
      STEP(e0, m0, e1, s + 0, true)
      STEP(e1, m1, e2, s + 1, false)
      STEP(e2, m2, e3, s + 2, false)
      STEP(e3, m3, e0, s + 3, false)
    }
    STEP(e0, m0, e1, 2045, true)
    STEP(e1, m1, e2, 2046, false)
    STEP(e2, m2, e3, 2047, false)
    #undef STEP

    // norm = M + log( sum_t p_t * exp(end_t) )
    float w = 0.f;
    if (act) w = p0 * __expf(endv[t0]) + p1 * __expf(endv[t1]);
    #pragma unroll
    for (int o = 16; o; o >>= 1) w += __shfl_xor_sync(0xffffffffu, w, o);
    if (L == 0) s_norm = Macc + (double)__logf(w);
  }

  __syncthreads();
  if (tid == 0) out[b] = s_score + (float)s_norm;
}

extern "C" void kernel_launch(void* const* d_in, const int* in_sizes, int n_in,
                              void* d_out, int out_size)
{
  const float* emissions       = (const float*)d_in[0];
  const void* tags             = d_in[1];
  const void* mask             = d_in[2];
  const float* trans           = (const float*)d_in[3];
  const float* startv          = (const float*)d_in[4];
  const float* endv            = (const float*)d_in[5];
  float* out                   = (float*)d_out;

  detect_fmt_kernel<<<1, 32>>>((const unsigned int*)tags, (const unsigned int*)mask);
  crf_fused_kernel<<<Bv, 64>>>(emissions, tags, mask, trans, startv, endv, out);
}